// round 3
// baseline (speedup 1.0000x reference)
#include <cuda_runtime.h>
#include <math.h>

// ---------------- problem constants ----------------
#define BG    64      // graphs
#define NA    32      // atoms per graph
#define HID   600
#define NG    50
#define NL    6
#define NTOT  (BG*NA)      // 2048
#define NE    (BG*NA*NA)   // 65536
#define PGRID 1023         // grid: t = d * PGRID/10, t in [0,1023]
#define PTAB  1027         // table rows: node r <-> d=(r-1)*h, r=0..1026

// ---------------- scratch layout (floats), every region 64-float aligned ----------------
#define AL64(x) (((x) + 63) & ~63)
#define O_H     0
#define O_XJ    AL64(O_H    + NTOT*HID)    // 1228800
#define O_M     AL64(O_XJ   + NTOT*HID)
#define O_T1    AL64(O_M    + NTOT*HID)
#define O_TAB   AL64(O_T1   + NTOT*HID)
#define O_TABA  AL64(O_TAB  + PTAB*HID)
#define O_RBFT  AL64(O_TABA + PTAB*HID)
#define O_COSW  AL64(O_RBFT + PTAB*NG)
#define O_TPOS  AL64(O_COSW + NE)
#define O_POOL  AL64(O_TPOS + NE)
#define SCRATCH_TOT AL64(O_POOL + BG*HID)

__device__ __align__(16) float g_scratch[SCRATCH_TOT];   // ~25.5 MB static scratch

// ---------------- helpers ----------------
__device__ __forceinline__ float sspf(float x) {
    // softplus(x) - log(2), numerically stable
    return fmaxf(x, 0.f) + log1pf(expf(-fabsf(x))) - 0.69314718055994531f;
}

#define FL_BIAS 1
#define FL_SSP  2
#define FL_RES  4

// ---------------- geometry: per-edge cosine cutoff + table position ----------------
__global__ void geom_k(const float* __restrict__ pos,
                       float* __restrict__ cosw, float* __restrict__ tpos) {
    int e = blockIdx.x * blockDim.x + threadIdx.x;
    if (e >= NE) return;
    int b = e >> 10;
    int r = e & 1023;
    int i = r >> 5, j = r & 31;
    int ai = b * NA + i, aj = b * NA + j;
    float dx = pos[ai*3+0] - pos[aj*3+0];
    float dy = pos[ai*3+1] - pos[aj*3+1];
    float dz = pos[ai*3+2] - pos[aj*3+2];
    float sq = dx*dx + dy*dy + dz*dz;
    float cw = 0.f, t = 0.f;
    if (i != j && sq <= 100.f) {
        float d = sqrtf(sq > 0.f ? sq : 1.f);   // matches reference safe-sqrt
        cw = 0.5f * (cospif(d * 0.1f) + 1.f);
        t  = d * ((float)PGRID / 10.f);
    }
    cosw[e] = cw;
    tpos[e] = t;
}

// ---------------- RBF values at table nodes (layer-independent) ----------------
__global__ void rbftab_k(float* __restrict__ rbfT) {
    int idx = blockIdx.x * blockDim.x + threadIdx.x;
    if (idx >= PTAB * NG) return;
    int p = idx / NG, g = idx % NG;
    float d   = (float)(p - 1) * (10.f / (float)PGRID);  // node r <-> d=(r-1)h
    float off = (float)g * (10.f / 49.f);                // linspace(0,10,50)
    float df  = d - off;
    const float coeff = -12.005f;                        // -0.5/(10/49)^2
    rbfT[idx] = expf(coeff * df * df);
}

// ---------------- atom embedding gather ----------------
__global__ void embed_k(const int* __restrict__ z, const float* __restrict__ emb,
                        float* __restrict__ h) {
    int idx = blockIdx.x * blockDim.x + threadIdx.x;
    if (idx >= NTOT * HID) return;
    int n = idx / HID, f = idx % HID;
    h[idx] = emb[z[n] * HID + f];
}

// ---------------- generic fp32 tiled GEMM: C = op(A[M,K] @ W[K,N] (+bias)) ----------------
// BM=BN=64, BK=8, 256 threads, 4x4 per thread
__global__ void gemm_k(const float* __restrict__ A, const float* __restrict__ W,
                       const float* __restrict__ bias, float* __restrict__ C,
                       int M, int N, int K, int flags) {
    __shared__ float As[8][64];
    __shared__ float Bs[8][64];
    int tid = threadIdx.x;
    int bm = blockIdx.y, bn = blockIdx.x;
    int row0 = bm * 64, col0 = bn * 64;
    int ty = tid >> 4, tx = tid & 15;

    float acc[4][4];
#pragma unroll
    for (int i = 0; i < 4; i++)
#pragma unroll
        for (int j = 0; j < 4; j++) acc[i][j] = 0.f;

    int kt = (K + 7) >> 3;
    for (int kb = 0; kb < kt; kb++) {
        int k0 = kb << 3;
        if (tid < 128) {
            // A tile: 64 rows x 8 k ; 128 threads x float4 along K
            int r  = tid >> 1;
            int kq = (tid & 1) << 2;
            int grow = row0 + r;
            float vx = 0.f, vy = 0.f, vz = 0.f, vw = 0.f;
            if (grow < M) {
                int kg = k0 + kq;
                if (((K & 3) == 0) && (kg + 3 < K)) {
                    float4 v = *(const float4*)(A + (size_t)grow * K + kg);
                    vx = v.x; vy = v.y; vz = v.z; vw = v.w;
                } else {
                    if (kg + 0 < K) vx = A[(size_t)grow * K + kg + 0];
                    if (kg + 1 < K) vy = A[(size_t)grow * K + kg + 1];
                    if (kg + 2 < K) vz = A[(size_t)grow * K + kg + 2];
                    if (kg + 3 < K) vw = A[(size_t)grow * K + kg + 3];
                }
            }
            As[kq + 0][r] = vx; As[kq + 1][r] = vy;
            As[kq + 2][r] = vz; As[kq + 3][r] = vw;
        } else {
            // B tile: 8 k x 64 cols ; 128 threads x float4 along N
            int u  = tid - 128;
            int kk = u >> 4;
            int c4 = (u & 15) << 2;
            int kg = k0 + kk;
            int gc = col0 + c4;
            float4 v = make_float4(0.f, 0.f, 0.f, 0.f);
            if (kg < K) {
                if (((N & 3) == 0) && (gc + 3 < N)) {
                    v = *(const float4*)(W + (size_t)kg * N + gc);
                } else {
                    if (gc + 0 < N) v.x = W[(size_t)kg * N + gc + 0];
                    if (gc + 1 < N) v.y = W[(size_t)kg * N + gc + 1];
                    if (gc + 2 < N) v.z = W[(size_t)kg * N + gc + 2];
                    if (gc + 3 < N) v.w = W[(size_t)kg * N + gc + 3];
                }
            }
            *(float4*)&Bs[kk][c4] = v;
        }
        __syncthreads();
#pragma unroll
        for (int k = 0; k < 8; k++) {
            float4 a = *(const float4*)&As[k][ty << 2];
            float4 b = *(const float4*)&Bs[k][tx << 2];
            float av[4] = {a.x, a.y, a.z, a.w};
            float bv[4] = {b.x, b.y, b.z, b.w};
#pragma unroll
            for (int i = 0; i < 4; i++)
#pragma unroll
                for (int j = 0; j < 4; j++)
                    acc[i][j] = fmaf(av[i], bv[j], acc[i][j]);
        }
        __syncthreads();
    }

#pragma unroll
    for (int i = 0; i < 4; i++) {
        int grow = row0 + (ty << 2) + i;
        if (grow >= M) continue;
#pragma unroll
        for (int j = 0; j < 4; j++) {
            int gc = col0 + (tx << 2) + j;
            if (gc >= N) continue;
            float v = acc[i][j];
            if (flags & FL_BIAS) v += bias[gc];
            if (flags & FL_SSP)  v = sspf(v);
            size_t idx = (size_t)grow * N + gc;
            if (flags & FL_RES)  v += C[idx];
            C[idx] = v;
        }
    }
}

// ---------------- message: m[b,i,f] = sum_j cosw * W_interp(d)[f] * xj[b,j,f] ----------------
__global__ void message_k(const float* __restrict__ cosw, const float* __restrict__ tpos,
                          const float* __restrict__ tab,  const float* __restrict__ xj,
                          float* __restrict__ m) {
    int bi = blockIdx.x;          // b*32 + i
    int b  = bi >> 5;
    int tid = threadIdx.x;        // 128 threads, 5 f-slices each
    float acc[5] = {0.f, 0.f, 0.f, 0.f, 0.f};

    for (int j = 0; j < NA; j++) {
        int e = bi * NA + j;
        float cw = cosw[e];
        if (cw == 0.f) continue;          // masked edge (block-uniform branch)
        float t = tpos[e];
        int u = (int)t;
        if (u > PGRID) u = PGRID;
        float s = t - (float)u;
        // 4-point Lagrange cubic weights (nodes u-1,u,u+1,u+2 -> table rows u..u+3)
        float sm1 = s - 1.f, sm2 = s - 2.f, sp1 = s + 1.f;
        float w0 = -s * sm1 * sm2 * (1.f / 6.f) * cw;
        float w1 =  sp1 * sm1 * sm2 * 0.5f       * cw;
        float w2 = -sp1 * s   * sm2 * 0.5f       * cw;
        float w3 =  sp1 * s   * sm1 * (1.f / 6.f) * cw;
        const float* T0 = tab + (size_t)u * HID;
        const float* xr = xj + (size_t)(b * NA + j) * HID;
#pragma unroll
        for (int k2 = 0; k2 < 5; k2++) {
            int f = tid + (k2 << 7);
            if (f < HID) {
                float wv = w0 * T0[f] + w1 * T0[HID + f]
                         + w2 * T0[2 * HID + f] + w3 * T0[3 * HID + f];
                acc[k2] = fmaf(wv, xr[f], acc[k2]);
            }
        }
    }
#pragma unroll
    for (int k2 = 0; k2 < 5; k2++) {
        int f = tid + (k2 << 7);
        if (f < HID) m[(size_t)bi * HID + f] = acc[k2];
    }
}

// ---------------- per-graph mean pool ----------------
__global__ void pool_k(const float* __restrict__ h, float* __restrict__ pool) {
    int idx = blockIdx.x * blockDim.x + threadIdx.x;
    if (idx >= BG * HID) return;
    int b = idx / HID, f = idx % HID;
    float s = 0.f;
#pragma unroll
    for (int i = 0; i < NA; i++) s += h[(size_t)(b * NA + i) * HID + f];
    pool[idx] = s * (1.f / (float)NA);
}

// ---------------- host launch ----------------
extern "C" void kernel_launch(void* const* d_in, const int* in_sizes, int n_in,
                              void* d_out, int out_size) {
    const int*   z    = (const int*)  d_in[0];
    const float* pos  = (const float*)d_in[1];
    // d_in[2] = batch (unused: equal-sized graphs)
    const float* emb  = (const float*)d_in[3];
    const float* w1   = (const float*)d_in[4];
    const float* b1   = (const float*)d_in[5];
    const float* w2   = (const float*)d_in[6];
    const float* b2   = (const float*)d_in[7];
    const float* l1w  = (const float*)d_in[8];
    const float* l2w  = (const float*)d_in[9];
    const float* l2b  = (const float*)d_in[10];
    const float* lw   = (const float*)d_in[11];
    const float* lb   = (const float*)d_in[12];
    const float* pw   = (const float*)d_in[13];
    const float* pb   = (const float*)d_in[14];
    float* out = (float*)d_out;

    float* S = nullptr;
    cudaGetSymbolAddress((void**)&S, g_scratch);   // no alloc, capture-safe
    float* H  = S + O_H;
    float* XJ = S + O_XJ;
    float* MM = S + O_M;
    float* T1 = S + O_T1;
    float* TB = S + O_TAB;
    float* TA = S + O_TABA;
    float* RB = S + O_RBFT;
    float* CW = S + O_COSW;
    float* TP = S + O_TPOS;
    float* PL = S + O_POOL;

    geom_k  <<<(NE + 255) / 256, 256>>>(pos, CW, TP);
    rbftab_k<<<(PTAB * NG + 255) / 256, 256>>>(RB);
    embed_k <<<(NTOT * HID + 255) / 256, 256>>>(z, emb, H);

    dim3 gN((HID + 63) / 64, (NTOT + 63) / 64);   // (10, 32)
    dim3 gT((HID + 63) / 64, (PTAB + 63) / 64);   // (10, 17)

    for (int L = 0; L < NL; L++) {
        const float* w1L  = w1  + (size_t)L * NG  * HID;
        const float* b1L  = b1  + (size_t)L * HID;
        const float* w2L  = w2  + (size_t)L * HID * HID;
        const float* b2L  = b2  + (size_t)L * HID;
        const float* l1wL = l1w + (size_t)L * HID * HID;
        const float* l2wL = l2w + (size_t)L * HID * HID;
        const float* l2bL = l2b + (size_t)L * HID;
        const float* lwL  = lw  + (size_t)L * HID * HID;
        const float* lbL  = lb  + (size_t)L * HID;

        // filter-table build: TA = ssp(RB @ w1 + b1) ; TB = TA @ w2 + b2
        gemm_k<<<gT, 256>>>(RB, w1L, b1L, TA, PTAB, HID, NG,  FL_BIAS | FL_SSP);
        gemm_k<<<gT, 256>>>(TA, w2L, b2L, TB, PTAB, HID, HID, FL_BIAS);
        // xj = h @ lin1 (no bias)
        gemm_k<<<gN, 256>>>(H, l1wL, nullptr, XJ, NTOT, HID, HID, 0);
        // fused interpolate + scatter-reduce message
        message_k<<<NTOT, 128>>>(CW, TP, TB, XJ, MM);
        // v = ssp(m @ l2w + l2b) @ lw + lb ; h += v
        gemm_k<<<gN, 256>>>(MM, l2wL, l2bL, T1, NTOT, HID, HID, FL_BIAS | FL_SSP);
        gemm_k<<<gN, 256>>>(T1, lwL,  lbL,  H,  NTOT, HID, HID, FL_BIAS | FL_RES);
    }

    pool_k<<<(BG * HID + 255) / 256, 256>>>(H, PL);
    gemm_k<<<dim3((HID + 63) / 64, 1), 256>>>(PL, pw, pb, out, BG, HID, HID, FL_BIAS);
}

// round 5
// speedup vs baseline: 1.1385x; 1.1385x over previous
#include <cuda_runtime.h>
#include <math.h>
#include <stdint.h>

// ---------------- problem constants ----------------
#define BG    64
#define NA    32
#define HID   600
#define NG    50
#define NL    6
#define NTOT  (BG*NA)      // 2048
#define NE    (BG*NA*NA)   // 65536
#define PGRID 2047         // t = d * PGRID/10 in [0,2047]
#define PTAB  2049         // rows 0..2048 ; row r <-> d = r*10/2047

// ---------------- scratch layout (floats), 64-float aligned regions ----------------
#define AL64(x) (((x) + 63) & ~63)
#define O_H     0
#define O_XJ    AL64(O_H    + NTOT*HID)
#define O_M     AL64(O_XJ   + NTOT*HID)
#define O_T1    AL64(O_M    + NTOT*HID)
#define O_TAB   AL64(O_T1   + NTOT*HID)
#define O_TABA  AL64(O_TAB  + PTAB*HID)
#define O_RBFT  AL64(O_TABA + PTAB*HID)
#define O_COSW  AL64(O_RBFT + PTAB*NG)
#define O_TPOS  AL64(O_COSW + NE)
#define O_POOL  AL64(O_TPOS + NE)
#define SCRATCH_TOT AL64(O_POOL + BG*HID)

__device__ __align__(16) float g_scratch[SCRATCH_TOT];   // ~30 MB static scratch

// ---------------- helpers ----------------
__device__ __forceinline__ float sspf(float x) {
    return fmaxf(x, 0.f) + log1pf(expf(-fabsf(x))) - 0.69314718055994531f;
}
__device__ __forceinline__ uint32_t f2tf(float x) {
    uint32_t r;
    asm("cvt.rna.tf32.f32 %0, %1;" : "=r"(r) : "f"(x));
    return r;
}

#define FL_BIAS 1
#define FL_SSP  2
#define FL_RES  4

// ---------------- geometry: per-edge cosine cutoff + table position ----------------
__global__ void geom_k(const float* __restrict__ pos,
                       float* __restrict__ cosw, float* __restrict__ tpos) {
    int e = blockIdx.x * blockDim.x + threadIdx.x;
    if (e >= NE) return;
    int b = e >> 10;
    int r = e & 1023;
    int i = r >> 5, j = r & 31;
    int ai = b * NA + i, aj = b * NA + j;
    float dx = pos[ai*3+0] - pos[aj*3+0];
    float dy = pos[ai*3+1] - pos[aj*3+1];
    float dz = pos[ai*3+2] - pos[aj*3+2];
    float sq = dx*dx + dy*dy + dz*dz;
    float cw = 0.f, t = 0.f;
    if (i != j && sq <= 100.f) {
        float d = sqrtf(sq > 0.f ? sq : 1.f);
        cw = 0.5f * (cospif(d * 0.1f) + 1.f);
        t  = d * ((float)PGRID / 10.f);
    }
    cosw[e] = cw;
    tpos[e] = t;
}

// ---------------- RBF values at table nodes ----------------
__global__ void rbftab_k(float* __restrict__ rbfT) {
    int idx = blockIdx.x * blockDim.x + threadIdx.x;
    if (idx >= PTAB * NG) return;
    int p = idx / NG, g = idx % NG;
    float d   = (float)p * (10.f / (float)PGRID);   // row r <-> d = r*h
    float off = (float)g * (10.f / 49.f);           // linspace(0,10,50)
    float df  = d - off;
    const float coeff = -12.005f;                   // -0.5/(10/49)^2
    rbfT[idx] = expf(coeff * df * df);
}

// ---------------- atom embedding gather ----------------
__global__ void embed_k(const int* __restrict__ z, const float* __restrict__ emb,
                        float* __restrict__ h) {
    int idx = blockIdx.x * blockDim.x + threadIdx.x;
    if (idx >= NTOT * HID) return;
    int n = idx / HID, f = idx % HID;
    h[idx] = emb[z[n] * HID + f];
}

// ---------------- tf32 tensor-core GEMM: C = op(A[M,K] @ W[K,N] (+bias)) ----------------
// BM=BN=64, BK=16, 128 threads (4 warps, 2x2), each warp 32x32 via m16n8k8 tf32 mma
__global__ __launch_bounds__(128) void gemm_tc(
        const float* __restrict__ A, const float* __restrict__ W,
        const float* __restrict__ bias, float* __restrict__ C,
        int M, int N, int K, int flags) {
    __shared__ uint32_t As[16][72];   // [k][m], stride 72 -> conflict-free frag loads
    __shared__ uint32_t Bs[16][72];   // [k][n]

    int tid  = threadIdx.x;
    int row0 = blockIdx.y * 64, col0 = blockIdx.x * 64;
    int warp = tid >> 5, lane = tid & 31;
    int wm = (warp >> 1) * 32, wn = (warp & 1) * 32;
    int g = lane >> 2, tig = lane & 3;

    bool k16 = ((K & 3) == 0);        // A rows 16B-aligned -> float4 path legal

    float c[2][4][4];
#pragma unroll
    for (int mi = 0; mi < 2; mi++)
#pragma unroll
        for (int ni = 0; ni < 4; ni++)
#pragma unroll
            for (int q = 0; q < 4; q++) c[mi][ni][q] = 0.f;

    for (int k0 = 0; k0 < K; k0 += 16) {
        // ---- A tile: 64 rows x 16 k ----
#pragma unroll
        for (int l = 0; l < 2; l++) {
            int idx = tid + l * 128;          // 0..255
            int r   = idx >> 2;               // 0..63
            int c4  = idx & 3;                // k-quad
            int grow = row0 + r;
            int kg   = k0 + c4 * 4;
            float v0 = 0.f, v1 = 0.f, v2 = 0.f, v3 = 0.f;
            if (grow < M) {
                if (k16 && (kg + 3 < K)) {
                    float4 t = *(const float4*)(A + (size_t)grow * K + kg);
                    v0 = t.x; v1 = t.y; v2 = t.z; v3 = t.w;
                } else {
                    if (kg + 0 < K) v0 = A[(size_t)grow * K + kg + 0];
                    if (kg + 1 < K) v1 = A[(size_t)grow * K + kg + 1];
                    if (kg + 2 < K) v2 = A[(size_t)grow * K + kg + 2];
                    if (kg + 3 < K) v3 = A[(size_t)grow * K + kg + 3];
                }
            }
            As[c4*4+0][r] = f2tf(v0);
            As[c4*4+1][r] = f2tf(v1);
            As[c4*4+2][r] = f2tf(v2);
            As[c4*4+3][r] = f2tf(v3);
        }
        // ---- B tile: 16 k x 64 cols ---- (N=600 always: 16B-aligned rows)
#pragma unroll
        for (int l = 0; l < 2; l++) {
            int idx = tid + l * 128;
            int kk  = idx >> 4;               // 0..15
            int c16 = idx & 15;
            int kg  = k0 + kk;
            int gc  = col0 + c16 * 4;
            float v0 = 0.f, v1 = 0.f, v2 = 0.f, v3 = 0.f;
            if (kg < K) {
                if (((N & 3) == 0) && (gc + 3 < N)) {
                    float4 t = *(const float4*)(W + (size_t)kg * N + gc);
                    v0 = t.x; v1 = t.y; v2 = t.z; v3 = t.w;
                } else {
                    if (gc + 0 < N) v0 = W[(size_t)kg * N + gc + 0];
                    if (gc + 1 < N) v1 = W[(size_t)kg * N + gc + 1];
                    if (gc + 2 < N) v2 = W[(size_t)kg * N + gc + 2];
                    if (gc + 3 < N) v3 = W[(size_t)kg * N + gc + 3];
                }
            }
            Bs[kk][c16*4+0] = f2tf(v0);
            Bs[kk][c16*4+1] = f2tf(v1);
            Bs[kk][c16*4+2] = f2tf(v2);
            Bs[kk][c16*4+3] = f2tf(v3);
        }
        __syncthreads();

#pragma unroll
        for (int ks = 0; ks < 2; ks++) {
            int kb = ks * 8;
            uint32_t a[2][4], b[4][2];
#pragma unroll
            for (int mi = 0; mi < 2; mi++) {
                int m = wm + mi * 16;
                a[mi][0] = As[kb + tig    ][m + g    ];
                a[mi][1] = As[kb + tig    ][m + g + 8];
                a[mi][2] = As[kb + tig + 4][m + g    ];
                a[mi][3] = As[kb + tig + 4][m + g + 8];
            }
#pragma unroll
            for (int ni = 0; ni < 4; ni++) {
                int n = wn + ni * 8;
                b[ni][0] = Bs[kb + tig    ][n + g];
                b[ni][1] = Bs[kb + tig + 4][n + g];
            }
#pragma unroll
            for (int mi = 0; mi < 2; mi++)
#pragma unroll
                for (int ni = 0; ni < 4; ni++) {
                    asm volatile(
                        "mma.sync.aligned.m16n8k8.row.col.f32.tf32.tf32.f32 "
                        "{%0,%1,%2,%3}, {%4,%5,%6,%7}, {%8,%9}, {%0,%1,%2,%3};\n"
                        : "+f"(c[mi][ni][0]), "+f"(c[mi][ni][1]),
                          "+f"(c[mi][ni][2]), "+f"(c[mi][ni][3])
                        : "r"(a[mi][0]), "r"(a[mi][1]), "r"(a[mi][2]), "r"(a[mi][3]),
                          "r"(b[ni][0]), "r"(b[ni][1]));
                }
        }
        __syncthreads();
    }

    // ---- epilogue ----
#pragma unroll
    for (int mi = 0; mi < 2; mi++) {
#pragma unroll
        for (int h01 = 0; h01 < 2; h01++) {
            int row = row0 + wm + mi * 16 + g + h01 * 8;
            if (row >= M) continue;
#pragma unroll
            for (int ni = 0; ni < 4; ni++) {
#pragma unroll
                for (int q = 0; q < 2; q++) {
                    int col = col0 + wn + ni * 8 + tig * 2 + q;
                    if (col >= N) continue;
                    float v = c[mi][ni][h01 * 2 + q];
                    if (flags & FL_BIAS) v += bias[col];
                    if (flags & FL_SSP)  v = sspf(v);
                    size_t idx = (size_t)row * N + col;
                    if (flags & FL_RES)  v += C[idx];
                    C[idx] = v;
                }
            }
        }
    }
}

// ---------------- message: m[b,i,f] = sum_j cosw * lerp(tab,d)[f] * xj[b,j,f] ----------------
__global__ __launch_bounds__(128) void message_k(
        const float* __restrict__ cosw, const float* __restrict__ tpos,
        const float* __restrict__ tab,  const float* __restrict__ xj,
        float* __restrict__ m) {
    int bi = blockIdx.x;          // b*32 + i
    int b  = bi >> 5;
    int tid = threadIdx.x;        // 128 threads; chunks tid and tid+128 of 150 float4
    float4 acc0 = make_float4(0.f, 0.f, 0.f, 0.f);
    float4 acc1 = make_float4(0.f, 0.f, 0.f, 0.f);
    const float* xb = xj + (size_t)(b * NA) * HID;

    for (int j = 0; j < NA; j++) {
        int e = bi * NA + j;
        float cw = cosw[e];
        if (cw == 0.f) continue;
        float t = tpos[e];
        int u = (int)t;
        if (u > PGRID) u = PGRID;
        float s  = t - (float)u;
        float w1 = s * cw;
        float w0 = cw - w1;
        const float4* T0 = (const float4*)(tab + (size_t)u * HID);
        const float4* T1 = (const float4*)(tab + (size_t)(u + 1) * HID);
        const float4* xr = (const float4*)(xb + (size_t)j * HID);
        {
            float4 t0 = T0[tid], t1 = T1[tid], x = xr[tid];
            acc0.x = fmaf(fmaf(w0, t0.x, w1 * t1.x), x.x, acc0.x);
            acc0.y = fmaf(fmaf(w0, t0.y, w1 * t1.y), x.y, acc0.y);
            acc0.z = fmaf(fmaf(w0, t0.z, w1 * t1.z), x.z, acc0.z);
            acc0.w = fmaf(fmaf(w0, t0.w, w1 * t1.w), x.w, acc0.w);
        }
        if (tid < 22) {
            int q = tid + 128;
            float4 t0 = T0[q], t1 = T1[q], x = xr[q];
            acc1.x = fmaf(fmaf(w0, t0.x, w1 * t1.x), x.x, acc1.x);
            acc1.y = fmaf(fmaf(w0, t0.y, w1 * t1.y), x.y, acc1.y);
            acc1.z = fmaf(fmaf(w0, t0.z, w1 * t1.z), x.z, acc1.z);
            acc1.w = fmaf(fmaf(w0, t0.w, w1 * t1.w), x.w, acc1.w);
        }
    }
    float4* mr = (float4*)(m + (size_t)bi * HID);
    mr[tid] = acc0;
    if (tid < 22) mr[tid + 128] = acc1;
}

// ---------------- per-graph mean pool ----------------
__global__ void pool_k(const float* __restrict__ h, float* __restrict__ pool) {
    int idx = blockIdx.x * blockDim.x + threadIdx.x;
    if (idx >= BG * HID) return;
    int b = idx / HID, f = idx % HID;
    float s = 0.f;
#pragma unroll
    for (int i = 0; i < NA; i++) s += h[(size_t)(b * NA + i) * HID + f];
    pool[idx] = s * (1.f / (float)NA);
}

// ---------------- host launch ----------------
extern "C" void kernel_launch(void* const* d_in, const int* in_sizes, int n_in,
                              void* d_out, int out_size) {
    const int*   z    = (const int*)  d_in[0];
    const float* pos  = (const float*)d_in[1];
    const float* emb  = (const float*)d_in[3];
    const float* w1   = (const float*)d_in[4];
    const float* b1   = (const float*)d_in[5];
    const float* w2   = (const float*)d_in[6];
    const float* b2   = (const float*)d_in[7];
    const float* l1w  = (const float*)d_in[8];
    const float* l2w  = (const float*)d_in[9];
    const float* l2b  = (const float*)d_in[10];
    const float* lw   = (const float*)d_in[11];
    const float* lb   = (const float*)d_in[12];
    const float* pw   = (const float*)d_in[13];
    const float* pb   = (const float*)d_in[14];
    float* out = (float*)d_out;

    float* S = nullptr;
    cudaGetSymbolAddress((void**)&S, g_scratch);
    float* H  = S + O_H;
    float* XJ = S + O_XJ;
    float* MM = S + O_M;
    float* T1 = S + O_T1;
    float* TB = S + O_TAB;
    float* TA = S + O_TABA;
    float* RB = S + O_RBFT;
    float* CW = S + O_COSW;
    float* TP = S + O_TPOS;
    float* PL = S + O_POOL;

    geom_k  <<<(NE + 255) / 256, 256>>>(pos, CW, TP);
    rbftab_k<<<(PTAB * NG + 255) / 256, 256>>>(RB);
    embed_k <<<(NTOT * HID + 255) / 256, 256>>>(z, emb, H);

    dim3 gN((HID + 63) / 64, (NTOT + 63) / 64);   // (10, 32)
    dim3 gT((HID + 63) / 64, (PTAB + 63) / 64);   // (10, 33)

    for (int L = 0; L < NL; L++) {
        const float* w1L  = w1  + (size_t)L * NG  * HID;
        const float* b1L  = b1  + (size_t)L * HID;
        const float* w2L  = w2  + (size_t)L * HID * HID;
        const float* b2L  = b2  + (size_t)L * HID;
        const float* l1wL = l1w + (size_t)L * HID * HID;
        const float* l2wL = l2w + (size_t)L * HID * HID;
        const float* l2bL = l2b + (size_t)L * HID;
        const float* lwL  = lw  + (size_t)L * HID * HID;
        const float* lbL  = lb  + (size_t)L * HID;

        // filter-table build: TA = ssp(RB @ w1 + b1) ; TB = TA @ w2 + b2
        gemm_tc<<<gT, 128>>>(RB, w1L, b1L, TA, PTAB, HID, NG,  FL_BIAS | FL_SSP);
        gemm_tc<<<gT, 128>>>(TA, w2L, b2L, TB, PTAB, HID, HID, FL_BIAS);
        // xj = h @ lin1 (no bias)
        gemm_tc<<<gN, 128>>>(H, l1wL, nullptr, XJ, NTOT, HID, HID, 0);
        // fused interpolate + scatter-reduce message
        message_k<<<NTOT, 128>>>(CW, TP, TB, XJ, MM);
        // v = ssp(m @ l2w + l2b) @ lw + lb ; h += v
        gemm_tc<<<gN, 128>>>(MM, l2wL, l2bL, T1, NTOT, HID, HID, FL_BIAS | FL_SSP);
        gemm_tc<<<gN, 128>>>(T1, lwL,  lbL,  H,  NTOT, HID, HID, FL_BIAS | FL_RES);
    }

    pool_k<<<(BG * HID + 255) / 256, 256>>>(H, PL);
    gemm_tc<<<dim3((HID + 63) / 64, 1), 128>>>(PL, pw, pb, out, BG, HID, HID, FL_BIAS);
}

// round 6
// speedup vs baseline: 1.7236x; 1.5139x over previous
#include <cuda_runtime.h>
#include <math.h>
#include <stdint.h>

// ---------------- problem constants ----------------
#define BG    64
#define NA    32
#define HID   600
#define NG    50
#define NL    6
#define NTOT  (BG*NA)      // 2048
#define NE    (BG*NA*NA)   // 65536
#define PGRID 2047         // t = d * PGRID/10 in [0,2047]
#define PTAB  2049         // rows 0..2048 ; row r <-> d = r*10/2047

// ---------------- scratch layout (floats), 64-float aligned regions ----------------
#define AL64(x) (((x) + 63) & ~63)
#define O_H     0
#define O_XJ    AL64(O_H    + NTOT*HID)
#define O_M     AL64(O_XJ   + NTOT*HID)
#define O_T1    AL64(O_M    + NTOT*HID)
#define O_TAB   AL64(O_T1   + NTOT*HID)
#define O_TABA  AL64(O_TAB  + PTAB*HID)
#define O_RBFT  AL64(O_TABA + PTAB*HID)
#define O_COSW  AL64(O_RBFT + PTAB*NG)
#define O_TPOS  AL64(O_COSW + NE)
#define O_POOL  AL64(O_TPOS + NE)
#define SCRATCH_TOT AL64(O_POOL + BG*HID)

__device__ __align__(16) float g_scratch[SCRATCH_TOT];   // ~30 MB static scratch

// ---------------- helpers ----------------
__device__ __forceinline__ float sspf(float x) {
    return fmaxf(x, 0.f) + log1pf(expf(-fabsf(x))) - 0.69314718055994531f;
}
__device__ __forceinline__ uint32_t f2tf(float x) {
    uint32_t r;
    asm("cvt.rna.tf32.f32 %0, %1;" : "=r"(r) : "f"(x));
    return r;
}

#define FL_BIAS 1
#define FL_SSP  2
#define FL_RES  4

// ---------------- geometry: per-edge cosine cutoff + table position ----------------
__global__ void geom_k(const float* __restrict__ pos,
                       float* __restrict__ cosw, float* __restrict__ tpos) {
    int e = blockIdx.x * blockDim.x + threadIdx.x;
    if (e >= NE) return;
    int b = e >> 10;
    int r = e & 1023;
    int i = r >> 5, j = r & 31;
    int ai = b * NA + i, aj = b * NA + j;
    float dx = pos[ai*3+0] - pos[aj*3+0];
    float dy = pos[ai*3+1] - pos[aj*3+1];
    float dz = pos[ai*3+2] - pos[aj*3+2];
    float sq = dx*dx + dy*dy + dz*dz;
    float cw = 0.f, t = 0.f;
    if (i != j && sq <= 100.f) {
        float d = sqrtf(sq > 0.f ? sq : 1.f);
        cw = 0.5f * (cospif(d * 0.1f) + 1.f);
        t  = d * ((float)PGRID / 10.f);
    }
    cosw[e] = cw;
    tpos[e] = t;
}

// ---------------- RBF values at table nodes ----------------
__global__ void rbftab_k(float* __restrict__ rbfT) {
    int idx = blockIdx.x * blockDim.x + threadIdx.x;
    if (idx >= PTAB * NG) return;
    int p = idx / NG, g = idx % NG;
    float d   = (float)p * (10.f / (float)PGRID);   // row r <-> d = r*h
    float off = (float)g * (10.f / 49.f);           // linspace(0,10,50)
    float df  = d - off;
    const float coeff = -12.005f;                   // -0.5/(10/49)^2
    rbfT[idx] = expf(coeff * df * df);
}

// ---------------- atom embedding gather ----------------
__global__ void embed_k(const int* __restrict__ z, const float* __restrict__ emb,
                        float* __restrict__ h) {
    int idx = blockIdx.x * blockDim.x + threadIdx.x;
    if (idx >= NTOT * HID) return;
    int n = idx / HID, f = idx % HID;
    h[idx] = emb[z[n] * HID + f];
}

// ---------------- tf32 tensor-core GEMM, software-pipelined ----------------
// C = op(A[M,K] @ W[K,N] (+bias)) ; BM=BN=64, BK=32, 128 threads (4 warps 2x2),
// warp tile 32x32 via m16n8k8 tf32 mma. Register double-buffer: LDG of tile
// kb+1 overlaps MMA on tile kb; cvt.rna at STS time.
__global__ __launch_bounds__(128) void gemm_tc(
        const float* __restrict__ A, const float* __restrict__ W,
        const float* __restrict__ bias, float* __restrict__ C,
        int M, int N, int K, int flags) {
    __shared__ uint32_t As[32][72];   // [k][m] tf32 bits, conflict-free frag loads
    __shared__ uint32_t Bs[32][72];   // [k][n]

    int tid  = threadIdx.x;
    int row0 = blockIdx.y * 64, col0 = blockIdx.x * 64;
    int warp = tid >> 5, lane = tid & 31;
    int wm = (warp >> 1) * 32, wn = (warp & 1) * 32;
    int g = lane >> 2, tig = lane & 3;

    bool k16 = ((K & 3) == 0);        // A rows 16B-aligned -> float4 path legal

    float c[2][4][4];
#pragma unroll
    for (int mi = 0; mi < 2; mi++)
#pragma unroll
        for (int ni = 0; ni < 4; ni++)
#pragma unroll
            for (int q = 0; q < 4; q++) c[mi][ni][q] = 0.f;

    float a_st[4][4], b_st[4][4];     // staging registers (one 64x32 tile each)

    // ---- stage loaders: global -> regs ----
    auto ldA = [&](int k0) {
#pragma unroll
        for (int l = 0; l < 4; l++) {
            int idx = tid + l * 128;          // 0..511
            int r   = idx >> 3;               // row 0..63
            int c4  = idx & 7;                // k-quad 0..7
            int grow = row0 + r;
            int kg   = k0 + c4 * 4;
            float v0 = 0.f, v1 = 0.f, v2 = 0.f, v3 = 0.f;
            if (grow < M) {
                if (k16 && (kg + 3 < K)) {
                    float4 t = *(const float4*)(A + (size_t)grow * K + kg);
                    v0 = t.x; v1 = t.y; v2 = t.z; v3 = t.w;
                } else {
                    if (kg + 0 < K) v0 = A[(size_t)grow * K + kg + 0];
                    if (kg + 1 < K) v1 = A[(size_t)grow * K + kg + 1];
                    if (kg + 2 < K) v2 = A[(size_t)grow * K + kg + 2];
                    if (kg + 3 < K) v3 = A[(size_t)grow * K + kg + 3];
                }
            }
            a_st[l][0] = v0; a_st[l][1] = v1; a_st[l][2] = v2; a_st[l][3] = v3;
        }
    };
    auto ldB = [&](int k0) {
#pragma unroll
        for (int l = 0; l < 4; l++) {
            int idx = tid + l * 128;
            int kk  = idx >> 4;               // k 0..31
            int c16 = idx & 15;               // n-quad 0..15
            int kg  = k0 + kk;
            int gc  = col0 + c16 * 4;
            float v0 = 0.f, v1 = 0.f, v2 = 0.f, v3 = 0.f;
            if (kg < K) {
                if (((N & 3) == 0) && (gc + 3 < N)) {
                    float4 t = *(const float4*)(W + (size_t)kg * N + gc);
                    v0 = t.x; v1 = t.y; v2 = t.z; v3 = t.w;
                } else {
                    if (gc + 0 < N) v0 = W[(size_t)kg * N + gc + 0];
                    if (gc + 1 < N) v1 = W[(size_t)kg * N + gc + 1];
                    if (gc + 2 < N) v2 = W[(size_t)kg * N + gc + 2];
                    if (gc + 3 < N) v3 = W[(size_t)kg * N + gc + 3];
                }
            }
            b_st[l][0] = v0; b_st[l][1] = v1; b_st[l][2] = v2; b_st[l][3] = v3;
        }
    };
    auto sts = [&]() {
#pragma unroll
        for (int l = 0; l < 4; l++) {
            int idx = tid + l * 128;
            int r   = idx >> 3;
            int c4  = idx & 7;
#pragma unroll
            for (int q = 0; q < 4; q++) As[c4 * 4 + q][r] = f2tf(a_st[l][q]);
            int kk  = idx >> 4;
            int c16 = idx & 15;
#pragma unroll
            for (int q = 0; q < 4; q++) Bs[kk][c16 * 4 + q] = f2tf(b_st[l][q]);
        }
    };

    int nk = (K + 31) >> 5;

    // prologue: tile 0 -> smem
    ldA(0); ldB(0);
    sts();
    __syncthreads();

    for (int kb = 0; kb < nk; kb++) {
        bool more = (kb + 1 < nk);
        if (more) { ldA((kb + 1) << 5); ldB((kb + 1) << 5); }  // LDGs in flight

        // ---- compute on resident tile: 4 k8-steps ----
#pragma unroll
        for (int ks = 0; ks < 4; ks++) {
            int kb8 = ks * 8;
            uint32_t a[2][4], b[4][2];
#pragma unroll
            for (int mi = 0; mi < 2; mi++) {
                int m = wm + mi * 16;
                a[mi][0] = As[kb8 + tig    ][m + g    ];
                a[mi][1] = As[kb8 + tig    ][m + g + 8];
                a[mi][2] = As[kb8 + tig + 4][m + g    ];
                a[mi][3] = As[kb8 + tig + 4][m + g + 8];
            }
#pragma unroll
            for (int ni = 0; ni < 4; ni++) {
                int n = wn + ni * 8;
                b[ni][0] = Bs[kb8 + tig    ][n + g];
                b[ni][1] = Bs[kb8 + tig + 4][n + g];
            }
#pragma unroll
            for (int mi = 0; mi < 2; mi++)
#pragma unroll
                for (int ni = 0; ni < 4; ni++) {
                    asm volatile(
                        "mma.sync.aligned.m16n8k8.row.col.f32.tf32.tf32.f32 "
                        "{%0,%1,%2,%3}, {%4,%5,%6,%7}, {%8,%9}, {%0,%1,%2,%3};\n"
                        : "+f"(c[mi][ni][0]), "+f"(c[mi][ni][1]),
                          "+f"(c[mi][ni][2]), "+f"(c[mi][ni][3])
                        : "r"(a[mi][0]), "r"(a[mi][1]), "r"(a[mi][2]), "r"(a[mi][3]),
                          "r"(b[ni][0]), "r"(b[ni][1]));
                }
        }
        if (more) {
            __syncthreads();   // all warps done reading current tile
            sts();             // cvt + store next tile
            __syncthreads();
        }
    }

    // ---- epilogue ----
#pragma unroll
    for (int mi = 0; mi < 2; mi++) {
#pragma unroll
        for (int h01 = 0; h01 < 2; h01++) {
            int row = row0 + wm + mi * 16 + g + h01 * 8;
            if (row >= M) continue;
#pragma unroll
            for (int ni = 0; ni < 4; ni++) {
#pragma unroll
                for (int q = 0; q < 2; q++) {
                    int col = col0 + wn + ni * 8 + tig * 2 + q;
                    if (col >= N) continue;
                    float v = c[mi][ni][h01 * 2 + q];
                    if (flags & FL_BIAS) v += bias[col];
                    if (flags & FL_SSP)  v = sspf(v);
                    size_t idx = (size_t)row * N + col;
                    if (flags & FL_RES)  v += C[idx];
                    C[idx] = v;
                }
            }
        }
    }
}

// ---------------- message: m[b,i,f] = sum_j cosw * lerp(tab,d)[f] * xj[b,j,f] ----------------
__global__ __launch_bounds__(128) void message_k(
        const float* __restrict__ cosw, const float* __restrict__ tpos,
        const float* __restrict__ tab,  const float* __restrict__ xj,
        float* __restrict__ m) {
    int bi = blockIdx.x;          // b*32 + i
    int b  = bi >> 5;
    int tid = threadIdx.x;        // 128 threads; chunks tid and tid+128 of 150 float4
    float4 acc0 = make_float4(0.f, 0.f, 0.f, 0.f);
    float4 acc1 = make_float4(0.f, 0.f, 0.f, 0.f);
    const float* xb = xj + (size_t)(b * NA) * HID;

    for (int j = 0; j < NA; j++) {
        int e = bi * NA + j;
        float cw = cosw[e];
        if (cw == 0.f) continue;
        float t = tpos[e];
        int u = (int)t;
        if (u > PGRID) u = PGRID;
        float s  = t - (float)u;
        float w1 = s * cw;
        float w0 = cw - w1;
        const float4* T0 = (const float4*)(tab + (size_t)u * HID);
        const float4* T1 = (const float4*)(tab + (size_t)(u + 1) * HID);
        const float4* xr = (const float4*)(xb + (size_t)j * HID);
        {
            float4 t0 = T0[tid], t1 = T1[tid], x = xr[tid];
            acc0.x = fmaf(fmaf(w0, t0.x, w1 * t1.x), x.x, acc0.x);
            acc0.y = fmaf(fmaf(w0, t0.y, w1 * t1.y), x.y, acc0.y);
            acc0.z = fmaf(fmaf(w0, t0.z, w1 * t1.z), x.z, acc0.z);
            acc0.w = fmaf(fmaf(w0, t0.w, w1 * t1.w), x.w, acc0.w);
        }
        if (tid < 22) {
            int q = tid + 128;
            float4 t0 = T0[q], t1 = T1[q], x = xr[q];
            acc1.x = fmaf(fmaf(w0, t0.x, w1 * t1.x), x.x, acc1.x);
            acc1.y = fmaf(fmaf(w0, t0.y, w1 * t1.y), x.y, acc1.y);
            acc1.z = fmaf(fmaf(w0, t0.z, w1 * t1.z), x.z, acc1.z);
            acc1.w = fmaf(fmaf(w0, t0.w, w1 * t1.w), x.w, acc1.w);
        }
    }
    float4* mr = (float4*)(m + (size_t)bi * HID);
    mr[tid] = acc0;
    if (tid < 22) mr[tid + 128] = acc1;
}

// ---------------- per-graph mean pool ----------------
__global__ void pool_k(const float* __restrict__ h, float* __restrict__ pool) {
    int idx = blockIdx.x * blockDim.x + threadIdx.x;
    if (idx >= BG * HID) return;
    int b = idx / HID, f = idx % HID;
    float s = 0.f;
#pragma unroll
    for (int i = 0; i < NA; i++) s += h[(size_t)(b * NA + i) * HID + f];
    pool[idx] = s * (1.f / (float)NA);
}

// ---------------- host launch ----------------
extern "C" void kernel_launch(void* const* d_in, const int* in_sizes, int n_in,
                              void* d_out, int out_size) {
    const int*   z    = (const int*)  d_in[0];
    const float* pos  = (const float*)d_in[1];
    const float* emb  = (const float*)d_in[3];
    const float* w1   = (const float*)d_in[4];
    const float* b1   = (const float*)d_in[5];
    const float* w2   = (const float*)d_in[6];
    const float* b2   = (const float*)d_in[7];
    const float* l1w  = (const float*)d_in[8];
    const float* l2w  = (const float*)d_in[9];
    const float* l2b  = (const float*)d_in[10];
    const float* lw   = (const float*)d_in[11];
    const float* lb   = (const float*)d_in[12];
    const float* pw   = (const float*)d_in[13];
    const float* pb   = (const float*)d_in[14];
    float* out = (float*)d_out;

    float* S = nullptr;
    cudaGetSymbolAddress((void**)&S, g_scratch);
    float* H  = S + O_H;
    float* XJ = S + O_XJ;
    float* MM = S + O_M;
    float* T1 = S + O_T1;
    float* TB = S + O_TAB;
    float* TA = S + O_TABA;
    float* RB = S + O_RBFT;
    float* CW = S + O_COSW;
    float* TP = S + O_TPOS;
    float* PL = S + O_POOL;

    geom_k  <<<(NE + 255) / 256, 256>>>(pos, CW, TP);
    rbftab_k<<<(PTAB * NG + 255) / 256, 256>>>(RB);
    embed_k <<<(NTOT * HID + 255) / 256, 256>>>(z, emb, H);

    dim3 gN((HID + 63) / 64, (NTOT + 63) / 64);   // (10, 32)
    dim3 gT((HID + 63) / 64, (PTAB + 63) / 64);   // (10, 33)

    for (int L = 0; L < NL; L++) {
        const float* w1L  = w1  + (size_t)L * NG  * HID;
        const float* b1L  = b1  + (size_t)L * HID;
        const float* w2L  = w2  + (size_t)L * HID * HID;
        const float* b2L  = b2  + (size_t)L * HID;
        const float* l1wL = l1w + (size_t)L * HID * HID;
        const float* l2wL = l2w + (size_t)L * HID * HID;
        const float* l2bL = l2b + (size_t)L * HID;
        const float* lwL  = lw  + (size_t)L * HID * HID;
        const float* lbL  = lb  + (size_t)L * HID;

        // filter-table build: TA = ssp(RB @ w1 + b1) ; TB = TA @ w2 + b2
        gemm_tc<<<gT, 128>>>(RB, w1L, b1L, TA, PTAB, HID, NG,  FL_BIAS | FL_SSP);
        gemm_tc<<<gT, 128>>>(TA, w2L, b2L, TB, PTAB, HID, HID, FL_BIAS);
        // xj = h @ lin1 (no bias)
        gemm_tc<<<gN, 128>>>(H, l1wL, nullptr, XJ, NTOT, HID, HID, 0);
        // fused interpolate + scatter-reduce message
        message_k<<<NTOT, 128>>>(CW, TP, TB, XJ, MM);
        // v = ssp(m @ l2w + l2b) @ lw + lb ; h += v
        gemm_tc<<<gN, 128>>>(MM, l2wL, l2bL, T1, NTOT, HID, HID, FL_BIAS | FL_SSP);
        gemm_tc<<<gN, 128>>>(T1, lwL,  lbL,  H,  NTOT, HID, HID, FL_BIAS | FL_RES);
    }

    pool_k<<<(BG * HID + 255) / 256, 256>>>(H, PL);
    gemm_tc<<<dim3((HID + 63) / 64, 1), 128>>>(PL, pw, pb, out, BG, HID, HID, FL_BIAS);
}